// round 12
// baseline (speedup 1.0000x reference)
#include <cuda_runtime.h>
#include <cuda_bf16.h>
#include <cstdint>

#define BB  2
#define NN  16384
#define MM  4096
#define C1_ 128
#define C2_ 256
#define H1_ 256
#define H2_ 128

// ---------------------------------------------------------------------------
// Scratch
// ---------------------------------------------------------------------------
__device__ int3   g_idx[BB * NN];
__device__ float3 g_wts[BB * NN];
__device__ float  g_Gt[(size_t)BB * MM * H1_];   // (B, M, H1) point-major
__device__ float  g_h [(size_t)BB * H1_ * NN];   // (B, H1, N) channel-major

// ---------------------------------------------------------------------------
// kNN (R1-proven): 1 thread per query, known points staged in 48KB smem.
// ---------------------------------------------------------------------------
__global__ void knn_kernel(const float* __restrict__ unknown,
                           const float* __restrict__ known,
                           int3* __restrict__ idx_out,
                           float3* __restrict__ wts_out)
{
    __shared__ float3 skn[MM];   // 49152B
    const int b = blockIdx.y;

    const float3* kn = (const float3*)known + (size_t)b * MM;
    for (int i = threadIdx.x; i < MM; i += blockDim.x) skn[i] = kn[i];
    __syncthreads();

    const int n = blockIdx.x * blockDim.x + threadIdx.x;
    const float3 p = ((const float3*)unknown)[(size_t)b * NN + n];

    float d0 = 1e30f, d1 = 1e30f, d2 = 1e30f;
    int   i0 = 0, i1 = 0, i2 = 0;

    #pragma unroll 4
    for (int m = 0; m < MM; m++) {
        float dx = skn[m].x - p.x;
        float dy = skn[m].y - p.y;
        float dz = skn[m].z - p.z;
        float d  = dx * dx + dy * dy + dz * dz;
        if (d < d2) {
            if (d < d1) {
                if (d < d0) { d2 = d1; i2 = i1; d1 = d0; i1 = i0; d0 = d; i0 = m; }
                else        { d2 = d1; i2 = i1; d1 = d;  i1 = m; }
            } else          { d2 = d;  i2 = m; }
        }
    }

    float r0 = 1.0f / (sqrtf(d0) + 1e-8f);
    float r1 = 1.0f / (sqrtf(d1) + 1e-8f);
    float r2 = 1.0f / (sqrtf(d2) + 1e-8f);
    float rs = 1.0f / (r0 + r1 + r2);

    idx_out[(size_t)b * NN + n] = make_int3(i0, i1, i2);
    wts_out[(size_t)b * NN + n] = make_float3(r0 * rs, r1 * rs, r2 * rs);
}

// ---------------------------------------------------------------------------
// Shared GEMM core: tile 128(O) x 128(P) x 16, 256 threads, 8x8 per thread,
// double-buffered smem, conflict-free operand maps (16B-stride chunks).
// Thread (tx,ty): o = o0 + {ty*4, 64+ty*4} + i;  p = p0 + {tx*4, 64+tx*4} + j.
// W staging: two row-chunks (wo, 64+wo) with wo=t>>2 (64B coalesced).
// ---------------------------------------------------------------------------
#define GEMM_PROLOG_AND_LOOP(Wm, ldW, Xb, P, K)                                     \
    __shared__ float Ws[2][16][128];                                                \
    __shared__ float Xs[2][16][128];                                                \
    const int t  = threadIdx.x;                                                     \
    const int tx = t & 15;                                                          \
    const int ty = t >> 4;                                                          \
    const int wo = t >> 2, wk = (t & 3) * 4;                                        \
    const int xk = t >> 4, xp = (t & 15) * 8;                                       \
    const float* wsrc0 = (Wm) + (long)(o0 + wo) * (ldW) + wk;                       \
    const float* wsrc1 = (Wm) + (long)(o0 + 64 + wo) * (ldW) + wk;                  \
    const float* xsrc  = (Xb) + (long)xk * (P) + p0 + xp;                           \
    float acc[8][8] = {};                                                           \
    {                                                                               \
        float4 wa = *(const float4*)&wsrc0[0];                                      \
        float4 wb = *(const float4*)&wsrc1[0];                                      \
        Ws[0][wk + 0][wo] = wa.x; Ws[0][wk + 1][wo] = wa.y;                         \
        Ws[0][wk + 2][wo] = wa.z; Ws[0][wk + 3][wo] = wa.w;                         \
        Ws[0][wk + 0][64 + wo] = wb.x; Ws[0][wk + 1][64 + wo] = wb.y;               \
        Ws[0][wk + 2][64 + wo] = wb.z; Ws[0][wk + 3][64 + wo] = wb.w;               \
        *(float4*)&Xs[0][xk][xp]     = *(const float4*)&xsrc[0];                    \
        *(float4*)&Xs[0][xk][xp + 4] = *(const float4*)&xsrc[4];                    \
    }                                                                               \
    __syncthreads();                                                                \
    int buf = 0;                                                                    \
    for (int k0 = 0; k0 < (K); k0 += 16) {                                          \
        const bool has_next = (k0 + 16 < (K));                                      \
        float4 wa, wb, x0, x1;                                                      \
        if (has_next) {                                                             \
            wa = *(const float4*)&wsrc0[k0 + 16];                                   \
            wb = *(const float4*)&wsrc1[k0 + 16];                                   \
            x0 = *(const float4*)&xsrc[(long)(k0 + 16) * (P)];                      \
            x1 = *(const float4*)&xsrc[(long)(k0 + 16) * (P) + 4];                  \
        }                                                                           \
        _Pragma("unroll")                                                           \
        for (int k = 0; k < 16; k++) {                                              \
            float a[8], bv[8];                                                      \
            *(float4*)&a[0]  = *(const float4*)&Ws[buf][k][ty * 4];                 \
            *(float4*)&a[4]  = *(const float4*)&Ws[buf][k][64 + ty * 4];            \
            *(float4*)&bv[0] = *(const float4*)&Xs[buf][k][tx * 4];                 \
            *(float4*)&bv[4] = *(const float4*)&Xs[buf][k][64 + tx * 4];            \
            _Pragma("unroll")                                                       \
            for (int i = 0; i < 8; i++)                                             \
                _Pragma("unroll")                                                   \
                for (int j = 0; j < 8; j++)                                         \
                    acc[i][j] = fmaf(a[i], bv[j], acc[i][j]);                       \
        }                                                                           \
        if (has_next) {                                                             \
            int nb = buf ^ 1;                                                       \
            Ws[nb][wk + 0][wo] = wa.x; Ws[nb][wk + 1][wo] = wa.y;                   \
            Ws[nb][wk + 2][wo] = wa.z; Ws[nb][wk + 3][wo] = wa.w;                   \
            Ws[nb][wk + 0][64 + wo] = wb.x; Ws[nb][wk + 1][64 + wo] = wb.y;         \
            Ws[nb][wk + 2][64 + wo] = wb.z; Ws[nb][wk + 3][64 + wo] = wb.w;         \
            *(float4*)&Xs[nb][xk][xp]     = x0;                                     \
            *(float4*)&Xs[nb][xk][xp + 4] = x1;                                     \
            __syncthreads();                                                        \
            buf = nb;                                                               \
        }                                                                           \
    }

// ---------------------------------------------------------------------------
// GEMM A: C stored point-major (P, O)   [for Gt]
// ---------------------------------------------------------------------------
__global__ void __launch_bounds__(256)
gemm_po_kernel(const float* __restrict__ Wm, int ldW,
               const float* __restrict__ X, long strideX,
               float* __restrict__ C, long strideC,
               int O, int P, int K)
{
    const float* Xb = X + (long)blockIdx.z * strideX;
    float*       Cb = C + (long)blockIdx.z * strideC;
    const int o0 = blockIdx.y * 128;
    const int p0 = blockIdx.x * 128;

    GEMM_PROLOG_AND_LOOP(Wm, ldW, Xb, P, K)

    #pragma unroll
    for (int ih = 0; ih < 2; ih++) {
        const int ot = o0 + ih * 64 + ty * 4;
        #pragma unroll
        for (int jh = 0; jh < 2; jh++) {
            const int pt = p0 + jh * 64 + tx * 4;
            #pragma unroll
            for (int j = 0; j < 4; j++) {
                float4 v = make_float4(acc[ih * 4 + 0][jh * 4 + j],
                                       acc[ih * 4 + 1][jh * 4 + j],
                                       acc[ih * 4 + 2][jh * 4 + j],
                                       acc[ih * 4 + 3][jh * 4 + j]);
                *(float4*)&Cb[(long)(pt + j) * O + ot] = v;
            }
        }
    }
}

// ---------------------------------------------------------------------------
// GEMM B (fused): Ut tile in regs + gather-interpolate Gt + bias + ReLU,
// stored channel-major (O, P) into h. Processed in two O-halves to bound regs.
// ---------------------------------------------------------------------------
__global__ void __launch_bounds__(256)
gemm_fused_kernel(const float* __restrict__ Wm, int ldW,
                  const float* __restrict__ X, long strideX,
                  const float* __restrict__ Gt,
                  const int3* __restrict__ idx,
                  const float3* __restrict__ wts,
                  const float* __restrict__ b1,
                  float* __restrict__ h,
                  int O, int P, int K)
{
    const int bz = blockIdx.z;
    const float* Xb = X + (long)bz * strideX;
    const int o0 = blockIdx.y * 128;
    const int p0 = blockIdx.x * 128;

    GEMM_PROLOG_AND_LOOP(Wm, ldW, Xb, P, K)

    const float* gbase = Gt + (long)bz * MM * H1_;
    float* hb = h + (long)bz * H1_ * NN;

    #pragma unroll
    for (int ih = 0; ih < 2; ih++) {
        const int ot = o0 + ih * 64 + ty * 4;
        const float4 bv4 = *(const float4*)&b1[ot];

        float hv[4][8];
        #pragma unroll
        for (int jj = 0; jj < 8; jj++) {
            const int n = p0 + ((jj < 4) ? (tx * 4 + jj) : (64 + tx * 4 + jj - 4));
            const int3   id = idx[(size_t)bz * NN + n];
            const float3 ww = wts[(size_t)bz * NN + n];
            float4 g0 = *(const float4*)&gbase[(long)id.x * H1_ + ot];
            float4 g1 = *(const float4*)&gbase[(long)id.y * H1_ + ot];
            float4 g2 = *(const float4*)&gbase[(long)id.z * H1_ + ot];
            hv[0][jj] = fmaxf(acc[ih * 4 + 0][jj] + ww.x * g0.x + ww.y * g1.x + ww.z * g2.x + bv4.x, 0.0f);
            hv[1][jj] = fmaxf(acc[ih * 4 + 1][jj] + ww.x * g0.y + ww.y * g1.y + ww.z * g2.y + bv4.y, 0.0f);
            hv[2][jj] = fmaxf(acc[ih * 4 + 2][jj] + ww.x * g0.z + ww.y * g1.z + ww.z * g2.z + bv4.z, 0.0f);
            hv[3][jj] = fmaxf(acc[ih * 4 + 3][jj] + ww.x * g0.w + ww.y * g1.w + ww.z * g2.w + bv4.w, 0.0f);
        }

        const int ptA = p0 + tx * 4;
        const int ptB = p0 + 64 + tx * 4;
        #pragma unroll
        for (int i = 0; i < 4; i++) {
            *(float4*)&hb[(long)(ot + i) * NN + ptA] = *(float4*)&hv[i][0];
            *(float4*)&hb[(long)(ot + i) * NN + ptB] = *(float4*)&hv[i][4];
        }
    }
}

// ---------------------------------------------------------------------------
// GEMM C: C stored (O, P) with bias + ReLU   [final output]
// ---------------------------------------------------------------------------
__global__ void __launch_bounds__(256)
gemm_op_kernel(const float* __restrict__ Wm, int ldW,
               const float* __restrict__ X, long strideX,
               float* __restrict__ C, long strideC,
               const float* __restrict__ bias,
               int O, int P, int K)
{
    const float* Xb = X + (long)blockIdx.z * strideX;
    float*       Cb = C + (long)blockIdx.z * strideC;
    const int o0 = blockIdx.y * 128;
    const int p0 = blockIdx.x * 128;

    GEMM_PROLOG_AND_LOOP(Wm, ldW, Xb, P, K)

    const int ptA = p0 + tx * 4;
    const int ptB = p0 + 64 + tx * 4;

    #pragma unroll
    for (int ih = 0; ih < 2; ih++) {
        const int ot = o0 + ih * 64 + ty * 4;
        const float4 bv4 = *(const float4*)&bias[ot];
        const float bb[4] = {bv4.x, bv4.y, bv4.z, bv4.w};

        #pragma unroll
        for (int i = 0; i < 4; i++) {
            float4 vA, vB;
            vA.x = fmaxf(acc[ih * 4 + i][0] + bb[i], 0.0f);
            vA.y = fmaxf(acc[ih * 4 + i][1] + bb[i], 0.0f);
            vA.z = fmaxf(acc[ih * 4 + i][2] + bb[i], 0.0f);
            vA.w = fmaxf(acc[ih * 4 + i][3] + bb[i], 0.0f);
            vB.x = fmaxf(acc[ih * 4 + i][4] + bb[i], 0.0f);
            vB.y = fmaxf(acc[ih * 4 + i][5] + bb[i], 0.0f);
            vB.z = fmaxf(acc[ih * 4 + i][6] + bb[i], 0.0f);
            vB.w = fmaxf(acc[ih * 4 + i][7] + bb[i], 0.0f);
            *(float4*)&Cb[(long)(ot + i) * P + ptA] = vA;
            *(float4*)&Cb[(long)(ot + i) * P + ptB] = vB;
        }
    }
}

// ---------------------------------------------------------------------------
// Launch
// ---------------------------------------------------------------------------
extern "C" void kernel_launch(void* const* d_in, const int* in_sizes, int n_in,
                              void* d_out, int out_size)
{
    const float* unknown      = (const float*)d_in[0];
    const float* known        = (const float*)d_in[1];
    const float* unknow_feats = (const float*)d_in[2];
    const float* known_feats  = (const float*)d_in[3];
    const float* W1           = (const float*)d_in[4];
    const float* b1           = (const float*)d_in[5];
    const float* W2           = (const float*)d_in[6];
    const float* b2           = (const float*)d_in[7];
    float* out = (float*)d_out;

    void *pGt, *pH, *pIdx, *pWts;
    cudaGetSymbolAddress(&pGt,  g_Gt);
    cudaGetSymbolAddress(&pH,   g_h);
    cudaGetSymbolAddress(&pIdx, g_idx);
    cudaGetSymbolAddress(&pWts, g_wts);

    // 1) 3-NN + weights (1 thread per query)
    knn_kernel<<<dim3(NN / 256, BB), 256>>>(unknown, known, (int3*)pIdx, (float3*)pWts);

    // 2) Gt[b,m,o] = sum_c W1[o,c] * known_feats[b,c,m]  (c in [0,256)), (P,O) store
    gemm_po_kernel<<<dim3(MM / 128, H1_ / 128, BB), 256>>>(
        W1, C1_ + C2_, known_feats, (long)C2_ * MM,
        (float*)pGt, (long)MM * H1_, H1_, MM, C2_);

    // 3+4) h = relu( W1b @ unknow_feats + gather-interp(Gt) + b1 ), (O,P) store
    gemm_fused_kernel<<<dim3(NN / 128, H1_ / 128, BB), 256>>>(
        W1 + C2_, C1_ + C2_, unknow_feats, (long)C1_ * NN,
        (const float*)pGt, (const int3*)pIdx, (const float3*)pWts,
        b1, (float*)pH, H1_, NN, C1_);

    // 5) out = relu(W2 @ h + b2), (O,P) store
    gemm_op_kernel<<<dim3(NN / 128, H2_ / 128, BB), 256>>>(
        W2, H1_, (const float*)pH, (long)H1_ * NN,
        out, (long)H2_ * NN, b2, H2_, NN, H1_);
}

// round 13
// speedup vs baseline: 1.1660x; 1.1660x over previous
#include <cuda_runtime.h>
#include <cuda_bf16.h>
#include <cstdint>

#define BB  2
#define NN  16384
#define MM  4096
#define C1_ 128
#define C2_ 256
#define H1_ 256
#define H2_ 128

// ---------------------------------------------------------------------------
// Scratch
// ---------------------------------------------------------------------------
__device__ int3   g_idx[BB * NN];
__device__ float3 g_wts[BB * NN];
__device__ float  g_Gt[(size_t)BB * MM * H1_];   // (B, M, H1) point-major
__device__ float  g_h [(size_t)BB * H1_ * NN];   // (B, H1, N) channel-major

// ---------------------------------------------------------------------------
// ins3: keep 3 smallest (score, index), stable earliest-wins on ties
// ---------------------------------------------------------------------------
__device__ __forceinline__ void ins3(float d, int i,
                                     float& s0, float& s1, float& s2,
                                     int& i0, int& i1, int& i2) {
    if (d < s2) {
        if (d < s1) {
            s2 = s1; i2 = i1;
            if (d < s0) { s1 = s0; i1 = i0; s0 = d; i0 = i; }
            else        { s1 = d;  i1 = i; }
        } else { s2 = d; i2 = i; }
    }
}

// ---------------------------------------------------------------------------
// Fused kNN + Gt-GEMM kernel (independent work, concurrent blocks).
//   blocks [0, 128)    : kNN — block i: b = i>>6, 256 queries each
//   blocks [128, 384)  : GEMM Gt = W1[:, :256] @ known_feats, (P,O) store
//                        j = i-128: px = j&31 (P/128), oy = (j>>5)&3 (O/64),
//                        bz = j>>7
// Dynamic smem 64KB: kNN uses 4x16KB SoA arrays; GEMM aliases first 24KB.
// ---------------------------------------------------------------------------
__global__ void __launch_bounds__(256)
knn_po_kernel(const float* __restrict__ unknown,
              const float* __restrict__ known,
              int3* __restrict__ idx_out,
              float3* __restrict__ wts_out,
              const float* __restrict__ Wm,     // W1 (ldW = C1_+C2_)
              const float* __restrict__ X,      // known_feats
              float* __restrict__ C)            // Gt
{
    extern __shared__ float dsm[];
    const int tid = threadIdx.x;

    if (blockIdx.x < 128) {
        // ================= kNN part =================
        const int b  = blockIdx.x >> 6;
        const int bx = blockIdx.x & 63;

        float* sx = dsm;
        float* sy = dsm + MM;
        float* sz = dsm + 2 * MM;
        float* sh = dsm + 3 * MM;

        const float* kb = known + (size_t)b * MM * 3;
        for (int i = tid; i < MM; i += 256) {
            float x = kb[i * 3 + 0], y = kb[i * 3 + 1], z = kb[i * 3 + 2];
            sx[i] = x; sy[i] = y; sz[i] = z;
            sh[i] = 0.5f * (x * x + y * y + z * z);
        }
        __syncthreads();

        const int n = bx * 256 + tid;
        const float3 p = ((const float3*)unknown)[(size_t)b * NN + n];
        const float nax = -p.x, nay = -p.y, naz = -p.z;

        float s0 = 1e30f, s1 = 1e30f, s2 = 1e30f;
        int i0 = 0, i1 = 0, i2 = 0;

        const float4* x4 = (const float4*)sx;
        const float4* y4 = (const float4*)sy;
        const float4* z4 = (const float4*)sz;
        const float4* h4 = (const float4*)sh;

        #pragma unroll 2
        for (int j = 0; j < MM / 4; j++) {
            float4 Xv = x4[j], Yv = y4[j], Zv = z4[j], Hv = h4[j];
            float t0 = fmaf(Xv.x, nax, fmaf(Yv.x, nay, fmaf(Zv.x, naz, Hv.x)));
            float t1 = fmaf(Xv.y, nax, fmaf(Yv.y, nay, fmaf(Zv.y, naz, Hv.y)));
            float t2 = fmaf(Xv.z, nax, fmaf(Yv.z, nay, fmaf(Zv.z, naz, Hv.z)));
            float t3 = fmaf(Xv.w, nax, fmaf(Yv.w, nay, fmaf(Zv.w, naz, Hv.w)));
            float m = fminf(fminf(t0, t1), fminf(t2, t3));
            if (m < s2) {
                int mb = j * 4;
                ins3(t0, mb + 0, s0, s1, s2, i0, i1, i2);
                ins3(t1, mb + 1, s0, s1, s2, i0, i1, i2);
                ins3(t2, mb + 2, s0, s1, s2, i0, i1, i2);
                ins3(t3, mb + 3, s0, s1, s2, i0, i1, i2);
            }
        }

        // exact distances for the winners
        float dx, dy, dz;
        dx = sx[i0] - p.x; dy = sy[i0] - p.y; dz = sz[i0] - p.z;
        float d0 = dx * dx + dy * dy + dz * dz;
        dx = sx[i1] - p.x; dy = sy[i1] - p.y; dz = sz[i1] - p.z;
        float d1 = dx * dx + dy * dy + dz * dz;
        dx = sx[i2] - p.x; dy = sy[i2] - p.y; dz = sz[i2] - p.z;
        float d2 = dx * dx + dy * dy + dz * dz;

        float r0 = 1.0f / (sqrtf(d0) + 1e-8f);
        float r1 = 1.0f / (sqrtf(d1) + 1e-8f);
        float r2 = 1.0f / (sqrtf(d2) + 1e-8f);
        float rs = 1.0f / (r0 + r1 + r2);

        idx_out[(size_t)b * NN + n] = make_int3(i0, i1, i2);
        wts_out[(size_t)b * NN + n] = make_float3(r0 * rs, r1 * rs, r2 * rs);
    } else {
        // ================= Gt GEMM part (64(O) x 128(P) x 16) =================
        const int j  = blockIdx.x - 128;
        const int o0 = ((j >> 5) & 3) * 64;
        const int p0 = (j & 31) * 128;
        const int bz = j >> 7;
        const int ldW = C1_ + C2_;
        const int P = MM, O = H1_, K = C2_;

        float* WsD = dsm;               // [2][16][64]
        float* XsD = dsm + 2 * 16 * 64; // [2][16][128]
        #define WsI(bf, k, o) WsD[((bf) * 16 + (k)) * 64 + (o)]
        #define XsI(bf, k, pp) XsD[((bf) * 16 + (k)) * 128 + (pp)]

        const float* Xb = X + (long)bz * C2_ * MM;
        float*       Cb = C + (long)bz * MM * H1_;

        const int tx = tid & 15;
        const int ty = tid >> 4;
        const int wo = tid >> 2, wk = (tid & 3) * 4;
        const int xk = tid >> 4, xp = (tid & 15) * 8;

        const float* wsrc = Wm + (long)(o0 + wo) * ldW + wk;
        const float* xsrc = Xb + (long)xk * P + p0 + xp;

        float acc[4][8] = {};

        {
            float4 wv = *(const float4*)&wsrc[0];
            WsI(0, wk + 0, wo) = wv.x; WsI(0, wk + 1, wo) = wv.y;
            WsI(0, wk + 2, wo) = wv.z; WsI(0, wk + 3, wo) = wv.w;
            *(float4*)&XsI(0, xk, xp)     = *(const float4*)&xsrc[0];
            *(float4*)&XsI(0, xk, xp + 4) = *(const float4*)&xsrc[4];
        }
        __syncthreads();

        int buf = 0;
        for (int k0 = 0; k0 < K; k0 += 16) {
            const bool has_next = (k0 + 16 < K);
            float4 wv, x0, x1;
            if (has_next) {
                wv = *(const float4*)&wsrc[k0 + 16];
                x0 = *(const float4*)&xsrc[(long)(k0 + 16) * P];
                x1 = *(const float4*)&xsrc[(long)(k0 + 16) * P + 4];
            }
            #pragma unroll
            for (int k = 0; k < 16; k++) {
                float a[4], bv[8];
                *(float4*)&a[0]  = *(const float4*)&WsI(buf, k, ty * 4);
                *(float4*)&bv[0] = *(const float4*)&XsI(buf, k, tx * 4);
                *(float4*)&bv[4] = *(const float4*)&XsI(buf, k, 64 + tx * 4);
                #pragma unroll
                for (int i = 0; i < 4; i++)
                    #pragma unroll
                    for (int jj = 0; jj < 8; jj++)
                        acc[i][jj] = fmaf(a[i], bv[jj], acc[i][jj]);
            }
            if (has_next) {
                int nb = buf ^ 1;
                WsI(nb, wk + 0, wo) = wv.x; WsI(nb, wk + 1, wo) = wv.y;
                WsI(nb, wk + 2, wo) = wv.z; WsI(nb, wk + 3, wo) = wv.w;
                *(float4*)&XsI(nb, xk, xp)     = x0;
                *(float4*)&XsI(nb, xk, xp + 4) = x1;
                __syncthreads();
                buf = nb;
            }
        }

        const int ot  = o0 + ty * 4;
        const int ptA = p0 + tx * 4;
        const int ptB = p0 + 64 + tx * 4;
        #pragma unroll
        for (int jj = 0; jj < 4; jj++) {
            float4 vA = make_float4(acc[0][jj],     acc[1][jj],     acc[2][jj],     acc[3][jj]);
            float4 vB = make_float4(acc[0][jj + 4], acc[1][jj + 4], acc[2][jj + 4], acc[3][jj + 4]);
            *(float4*)&Cb[(long)(ptA + jj) * O + ot] = vA;
            *(float4*)&Cb[(long)(ptB + jj) * O + ot] = vB;
        }
        #undef WsI
        #undef XsI
    }
}

// ---------------------------------------------------------------------------
// Shared GEMM core (R11): tile 64(O) x 128(P) x 16, 256 threads, 4x8/thread,
// double-buffered, conflict-free maps.
// ---------------------------------------------------------------------------
#define GEMM_PROLOG_AND_LOOP(Wm, ldW, Xb, P, K)                                     \
    __shared__ float Ws[2][16][64];                                                 \
    __shared__ float Xs[2][16][128];                                                \
    const int t  = threadIdx.x;                                                     \
    const int tx = t & 15;                                                          \
    const int ty = t >> 4;                                                          \
    const int wo = t >> 2, wk = (t & 3) * 4;                                        \
    const int xk = t >> 4, xp = (t & 15) * 8;                                       \
    const float* wsrc = (Wm) + (long)(o0 + wo) * (ldW) + wk;                        \
    const float* xsrc = (Xb) + (long)xk * (P) + p0 + xp;                            \
    float acc[4][8] = {};                                                           \
    {                                                                               \
        float4 wv = *(const float4*)&wsrc[0];                                       \
        Ws[0][wk + 0][wo] = wv.x; Ws[0][wk + 1][wo] = wv.y;                         \
        Ws[0][wk + 2][wo] = wv.z; Ws[0][wk + 3][wo] = wv.w;                         \
        *(float4*)&Xs[0][xk][xp]     = *(const float4*)&xsrc[0];                    \
        *(float4*)&Xs[0][xk][xp + 4] = *(const float4*)&xsrc[4];                    \
    }                                                                               \
    __syncthreads();                                                                \
    int buf = 0;                                                                    \
    for (int k0 = 0; k0 < (K); k0 += 16) {                                          \
        const bool has_next = (k0 + 16 < (K));                                      \
        float4 wv, x0, x1;                                                          \
        if (has_next) {                                                             \
            wv = *(const float4*)&wsrc[k0 + 16];                                    \
            x0 = *(const float4*)&xsrc[(long)(k0 + 16) * (P)];                      \
            x1 = *(const float4*)&xsrc[(long)(k0 + 16) * (P) + 4];                  \
        }                                                                           \
        _Pragma("unroll")                                                           \
        for (int k = 0; k < 16; k++) {                                              \
            float a[4], bv[8];                                                      \
            *(float4*)&a[0]  = *(const float4*)&Ws[buf][k][ty * 4];                 \
            *(float4*)&bv[0] = *(const float4*)&Xs[buf][k][tx * 4];                 \
            *(float4*)&bv[4] = *(const float4*)&Xs[buf][k][64 + tx * 4];            \
            _Pragma("unroll")                                                       \
            for (int i = 0; i < 4; i++)                                             \
                _Pragma("unroll")                                                   \
                for (int j = 0; j < 8; j++)                                         \
                    acc[i][j] = fmaf(a[i], bv[j], acc[i][j]);                       \
        }                                                                           \
        if (has_next) {                                                             \
            int nb = buf ^ 1;                                                       \
            Ws[nb][wk + 0][wo] = wv.x; Ws[nb][wk + 1][wo] = wv.y;                   \
            Ws[nb][wk + 2][wo] = wv.z; Ws[nb][wk + 3][wo] = wv.w;                   \
            *(float4*)&Xs[nb][xk][xp]     = x0;                                     \
            *(float4*)&Xs[nb][xk][xp + 4] = x1;                                     \
            __syncthreads();                                                        \
            buf = nb;                                                               \
        }                                                                           \
    }

// ---------------------------------------------------------------------------
// GEMM B (fused): Ut tile in regs + gather-interpolate Gt + bias + ReLU,
// stored channel-major (O, P) into h.
// ---------------------------------------------------------------------------
__global__ void __launch_bounds__(256)
gemm_fused_kernel(const float* __restrict__ Wm, int ldW,
                  const float* __restrict__ X, long strideX,
                  const float* __restrict__ Gt,
                  const int3* __restrict__ idx,
                  const float3* __restrict__ wts,
                  const float* __restrict__ b1,
                  float* __restrict__ h,
                  int O, int P, int K)
{
    const int bz = blockIdx.z;
    const float* Xb = X + (long)bz * strideX;
    const int o0 = blockIdx.y * 64;
    const int p0 = blockIdx.x * 128;

    GEMM_PROLOG_AND_LOOP(Wm, ldW, Xb, P, K)

    const int ot = o0 + ty * 4;

    const float4 bv4 = *(const float4*)&b1[ot];
    const float* gbase = Gt + (long)bz * MM * H1_;

    float hv[4][8];
    #pragma unroll
    for (int jj = 0; jj < 8; jj++) {
        const int n = p0 + ((jj < 4) ? (tx * 4 + jj) : (64 + tx * 4 + jj - 4));
        const int3   id = idx[(size_t)bz * NN + n];
        const float3 ww = wts[(size_t)bz * NN + n];
        float4 g0 = *(const float4*)&gbase[(long)id.x * H1_ + ot];
        float4 g1 = *(const float4*)&gbase[(long)id.y * H1_ + ot];
        float4 g2 = *(const float4*)&gbase[(long)id.z * H1_ + ot];
        hv[0][jj] = fmaxf(acc[0][jj] + ww.x * g0.x + ww.y * g1.x + ww.z * g2.x + bv4.x, 0.0f);
        hv[1][jj] = fmaxf(acc[1][jj] + ww.x * g0.y + ww.y * g1.y + ww.z * g2.y + bv4.y, 0.0f);
        hv[2][jj] = fmaxf(acc[2][jj] + ww.x * g0.z + ww.y * g1.z + ww.z * g2.z + bv4.z, 0.0f);
        hv[3][jj] = fmaxf(acc[3][jj] + ww.x * g0.w + ww.y * g1.w + ww.z * g2.w + bv4.w, 0.0f);
    }

    float* hb = h + (long)bz * H1_ * NN;
    const int ptA = p0 + tx * 4;
    const int ptB = p0 + 64 + tx * 4;
    #pragma unroll
    for (int i = 0; i < 4; i++) {
        *(float4*)&hb[(long)(ot + i) * NN + ptA] = *(float4*)&hv[i][0];
        *(float4*)&hb[(long)(ot + i) * NN + ptB] = *(float4*)&hv[i][4];
    }
}

// ---------------------------------------------------------------------------
// GEMM C: C stored (O, P) with bias + ReLU   [final output]
// ---------------------------------------------------------------------------
__global__ void __launch_bounds__(256)
gemm_op_kernel(const float* __restrict__ Wm, int ldW,
               const float* __restrict__ X, long strideX,
               float* __restrict__ C, long strideC,
               const float* __restrict__ bias,
               int O, int P, int K)
{
    const float* Xb = X + (long)blockIdx.z * strideX;
    float*       Cb = C + (long)blockIdx.z * strideC;
    const int o0 = blockIdx.y * 64;
    const int p0 = blockIdx.x * 128;

    GEMM_PROLOG_AND_LOOP(Wm, ldW, Xb, P, K)

    const int ot  = o0 + ty * 4;
    const int ptA = p0 + tx * 4;
    const int ptB = p0 + 64 + tx * 4;
    const float4 bv4 = *(const float4*)&bias[ot];
    const float bb[4] = {bv4.x, bv4.y, bv4.z, bv4.w};

    #pragma unroll
    for (int i = 0; i < 4; i++) {
        float4 vA, vB;
        vA.x = fmaxf(acc[i][0] + bb[i], 0.0f);
        vA.y = fmaxf(acc[i][1] + bb[i], 0.0f);
        vA.z = fmaxf(acc[i][2] + bb[i], 0.0f);
        vA.w = fmaxf(acc[i][3] + bb[i], 0.0f);
        vB.x = fmaxf(acc[i][4] + bb[i], 0.0f);
        vB.y = fmaxf(acc[i][5] + bb[i], 0.0f);
        vB.z = fmaxf(acc[i][6] + bb[i], 0.0f);
        vB.w = fmaxf(acc[i][7] + bb[i], 0.0f);
        *(float4*)&Cb[(long)(ot + i) * P + ptA] = vA;
        *(float4*)&Cb[(long)(ot + i) * P + ptB] = vB;
    }
}

// ---------------------------------------------------------------------------
// Launch
// ---------------------------------------------------------------------------
extern "C" void kernel_launch(void* const* d_in, const int* in_sizes, int n_in,
                              void* d_out, int out_size)
{
    const float* unknown      = (const float*)d_in[0];
    const float* known        = (const float*)d_in[1];
    const float* unknow_feats = (const float*)d_in[2];
    const float* known_feats  = (const float*)d_in[3];
    const float* W1           = (const float*)d_in[4];
    const float* b1           = (const float*)d_in[5];
    const float* W2           = (const float*)d_in[6];
    const float* b2           = (const float*)d_in[7];
    float* out = (float*)d_out;

    void *pGt, *pH, *pIdx, *pWts;
    cudaGetSymbolAddress(&pGt,  g_Gt);
    cudaGetSymbolAddress(&pH,   g_h);
    cudaGetSymbolAddress(&pIdx, g_idx);
    cudaGetSymbolAddress(&pWts, g_wts);

    const int fused_smem = 4 * MM * 4;   // 64KB
    cudaFuncSetAttribute(knn_po_kernel, cudaFuncAttributeMaxDynamicSharedMemorySize, fused_smem);

    // 1+2) kNN (blocks 0-127) + Gt GEMM (blocks 128-383), concurrent
    knn_po_kernel<<<384, 256, fused_smem>>>(
        unknown, known, (int3*)pIdx, (float3*)pWts,
        W1, known_feats, (float*)pGt);

    // 3+4) h = relu( W1b @ unknow_feats + gather-interp(Gt) + b1 ), (O,P) store
    gemm_fused_kernel<<<dim3(NN / 128, H1_ / 64, BB), 256>>>(
        W1 + C2_, C1_ + C2_, unknow_feats, (long)C1_ * NN,
        (const float*)pGt, (const int3*)pIdx, (const float3*)pWts,
        b1, (float*)pH, H1_, NN, C1_);

    // 5) out = relu(W2 @ h + b2), (O,P) store
    gemm_op_kernel<<<dim3(NN / 128, H2_ / 64, BB), 256>>>(
        W2, H1_, (const float*)pH, (long)H1_ * NN,
        out, (long)H2_ * NN, b2, H2_, NN, H1_);
}

// round 15
// speedup vs baseline: 1.7659x; 1.5146x over previous
#include <cuda_runtime.h>
#include <cuda_bf16.h>
#include <cstdint>

#define BB  2
#define NN  16384
#define MM  4096
#define C1_ 128
#define C2_ 256
#define H1_ 256
#define H2_ 128

// ---------------------------------------------------------------------------
// Scratch
// ---------------------------------------------------------------------------
__device__ int3   g_idx[BB * NN];
__device__ float3 g_wts[BB * NN];
__device__ float  g_Gt[(size_t)BB * MM * H1_];   // (B, M, H1) point-major
__device__ float  g_h [(size_t)BB * H1_ * NN];   // (B, H1, N) channel-major

// ---------------------------------------------------------------------------
// ins3: keep 3 smallest (score, index), stable earliest-wins on ties
// ---------------------------------------------------------------------------
__device__ __forceinline__ void ins3(float d, int i,
                                     float& s0, float& s1, float& s2,
                                     int& i0, int& i1, int& i2) {
    if (d < s2) {
        if (d < s1) {
            s2 = s1; i2 = i1;
            if (d < s0) { s1 = s0; i1 = i0; s0 = d; i0 = i; }
            else        { s1 = d;  i1 = i; }
        } else { s2 = d; i2 = i; }
    }
}

// ---------------------------------------------------------------------------
// kNN (SoA + half-norm score, verified in R13): 1 thread per query.
// score(m) = 0.5*|b_m|^2 - a.b_m  (monotone in |a-b|^2); winners re-scored
// with exact distances so the output weights match the reference bitwise
// behaviour of the direct version.
// ---------------------------------------------------------------------------
__global__ void __launch_bounds__(256)
knn_kernel(const float* __restrict__ unknown,
           const float* __restrict__ known,
           int3* __restrict__ idx_out,
           float3* __restrict__ wts_out)
{
    extern __shared__ float dsm[];
    float* sx = dsm;
    float* sy = dsm + MM;
    float* sz = dsm + 2 * MM;
    float* sh = dsm + 3 * MM;

    const int b   = blockIdx.y;
    const int tid = threadIdx.x;

    const float* kb = known + (size_t)b * MM * 3;
    for (int i = tid; i < MM; i += 256) {
        float x = kb[i * 3 + 0], y = kb[i * 3 + 1], z = kb[i * 3 + 2];
        sx[i] = x; sy[i] = y; sz[i] = z;
        sh[i] = 0.5f * (x * x + y * y + z * z);
    }
    __syncthreads();

    const int n = blockIdx.x * 256 + tid;
    const float3 p = ((const float3*)unknown)[(size_t)b * NN + n];
    const float nax = -p.x, nay = -p.y, naz = -p.z;

    float s0 = 1e30f, s1 = 1e30f, s2 = 1e30f;
    int i0 = 0, i1 = 0, i2 = 0;

    const float4* x4 = (const float4*)sx;
    const float4* y4 = (const float4*)sy;
    const float4* z4 = (const float4*)sz;
    const float4* h4 = (const float4*)sh;

    #pragma unroll 2
    for (int j = 0; j < MM / 4; j++) {
        float4 Xv = x4[j], Yv = y4[j], Zv = z4[j], Hv = h4[j];
        float t0 = fmaf(Xv.x, nax, fmaf(Yv.x, nay, fmaf(Zv.x, naz, Hv.x)));
        float t1 = fmaf(Xv.y, nax, fmaf(Yv.y, nay, fmaf(Zv.y, naz, Hv.y)));
        float t2 = fmaf(Xv.z, nax, fmaf(Yv.z, nay, fmaf(Zv.z, naz, Hv.z)));
        float t3 = fmaf(Xv.w, nax, fmaf(Yv.w, nay, fmaf(Zv.w, naz, Hv.w)));
        float m = fminf(fminf(t0, t1), fminf(t2, t3));
        if (m < s2) {
            int mb = j * 4;
            ins3(t0, mb + 0, s0, s1, s2, i0, i1, i2);
            ins3(t1, mb + 1, s0, s1, s2, i0, i1, i2);
            ins3(t2, mb + 2, s0, s1, s2, i0, i1, i2);
            ins3(t3, mb + 3, s0, s1, s2, i0, i1, i2);
        }
    }

    // exact distances for the winners
    float dx, dy, dz;
    dx = sx[i0] - p.x; dy = sy[i0] - p.y; dz = sz[i0] - p.z;
    float d0 = dx * dx + dy * dy + dz * dz;
    dx = sx[i1] - p.x; dy = sy[i1] - p.y; dz = sz[i1] - p.z;
    float d1 = dx * dx + dy * dy + dz * dz;
    dx = sx[i2] - p.x; dy = sy[i2] - p.y; dz = sz[i2] - p.z;
    float d2 = dx * dx + dy * dy + dz * dz;

    float r0 = 1.0f / (sqrtf(d0) + 1e-8f);
    float r1 = 1.0f / (sqrtf(d1) + 1e-8f);
    float r2 = 1.0f / (sqrtf(d2) + 1e-8f);
    float rs = 1.0f / (r0 + r1 + r2);

    idx_out[(size_t)b * NN + n] = make_int3(i0, i1, i2);
    wts_out[(size_t)b * NN + n] = make_float3(r0 * rs, r1 * rs, r2 * rs);
}

// ---------------------------------------------------------------------------
// Shared GEMM core (R11): tile 64(O) x 128(P) x 16, 256 threads, 4x8/thread,
// double-buffered, conflict-free maps.
// ---------------------------------------------------------------------------
#define GEMM_PROLOG_AND_LOOP(Wm, ldW, Xb, P, K)                                     \
    __shared__ float Ws[2][16][64];                                                 \
    __shared__ float Xs[2][16][128];                                                \
    const int t  = threadIdx.x;                                                     \
    const int tx = t & 15;                                                          \
    const int ty = t >> 4;                                                          \
    const int wo = t >> 2, wk = (t & 3) * 4;                                        \
    const int xk = t >> 4, xp = (t & 15) * 8;                                       \
    const float* wsrc = (Wm) + (long)(o0 + wo) * (ldW) + wk;                        \
    const float* xsrc = (Xb) + (long)xk * (P) + p0 + xp;                            \
    float acc[4][8] = {};                                                           \
    {                                                                               \
        float4 wv = *(const float4*)&wsrc[0];                                       \
        Ws[0][wk + 0][wo] = wv.x; Ws[0][wk + 1][wo] = wv.y;                         \
        Ws[0][wk + 2][wo] = wv.z; Ws[0][wk + 3][wo] = wv.w;                         \
        *(float4*)&Xs[0][xk][xp]     = *(const float4*)&xsrc[0];                    \
        *(float4*)&Xs[0][xk][xp + 4] = *(const float4*)&xsrc[4];                    \
    }                                                                               \
    __syncthreads();                                                                \
    int buf = 0;                                                                    \
    for (int k0 = 0; k0 < (K); k0 += 16) {                                          \
        const bool has_next = (k0 + 16 < (K));                                      \
        float4 wv, x0, x1;                                                          \
        if (has_next) {                                                             \
            wv = *(const float4*)&wsrc[k0 + 16];                                    \
            x0 = *(const float4*)&xsrc[(long)(k0 + 16) * (P)];                      \
            x1 = *(const float4*)&xsrc[(long)(k0 + 16) * (P) + 4];                  \
        }                                                                           \
        _Pragma("unroll")                                                           \
        for (int k = 0; k < 16; k++) {                                              \
            float a[4], bv[8];                                                      \
            *(float4*)&a[0]  = *(const float4*)&Ws[buf][k][ty * 4];                 \
            *(float4*)&bv[0] = *(const float4*)&Xs[buf][k][tx * 4];                 \
            *(float4*)&bv[4] = *(const float4*)&Xs[buf][k][64 + tx * 4];            \
            _Pragma("unroll")                                                       \
            for (int i = 0; i < 4; i++)                                             \
                _Pragma("unroll")                                                   \
                for (int j = 0; j < 8; j++)                                         \
                    acc[i][j] = fmaf(a[i], bv[j], acc[i][j]);                       \
        }                                                                           \
        if (has_next) {                                                             \
            int nb = buf ^ 1;                                                       \
            Ws[nb][wk + 0][wo] = wv.x; Ws[nb][wk + 1][wo] = wv.y;                   \
            Ws[nb][wk + 2][wo] = wv.z; Ws[nb][wk + 3][wo] = wv.w;                   \
            *(float4*)&Xs[nb][xk][xp]     = x0;                                     \
            *(float4*)&Xs[nb][xk][xp + 4] = x1;                                     \
            __syncthreads();                                                        \
            buf = nb;                                                               \
        }                                                                           \
    }

// ---------------------------------------------------------------------------
// GEMM A: C stored point-major (P, O)   [for Gt]
// ---------------------------------------------------------------------------
__global__ void __launch_bounds__(256)
gemm_po_kernel(const float* __restrict__ Wm, int ldW,
               const float* __restrict__ X, long strideX,
               float* __restrict__ C, long strideC,
               int O, int P, int K)
{
    const float* Xb = X + (long)blockIdx.z * strideX;
    float*       Cb = C + (long)blockIdx.z * strideC;
    const int o0 = blockIdx.y * 64;
    const int p0 = blockIdx.x * 128;

    GEMM_PROLOG_AND_LOOP(Wm, ldW, Xb, P, K)

    const int ot  = o0 + ty * 4;
    const int ptA = p0 + tx * 4;
    const int ptB = p0 + 64 + tx * 4;
    #pragma unroll
    for (int j = 0; j < 4; j++) {
        float4 vA = make_float4(acc[0][j],     acc[1][j],     acc[2][j],     acc[3][j]);
        float4 vB = make_float4(acc[0][j + 4], acc[1][j + 4], acc[2][j + 4], acc[3][j + 4]);
        *(float4*)&Cb[(long)(ptA + j) * O + ot] = vA;
        *(float4*)&Cb[(long)(ptB + j) * O + ot] = vB;
    }
}

// ---------------------------------------------------------------------------
// GEMM B (fused): Ut tile in regs + gather-interpolate Gt + bias + ReLU,
// stored channel-major (O, P) into h.
// ---------------------------------------------------------------------------
__global__ void __launch_bounds__(256)
gemm_fused_kernel(const float* __restrict__ Wm, int ldW,
                  const float* __restrict__ X, long strideX,
                  const float* __restrict__ Gt,
                  const int3* __restrict__ idx,
                  const float3* __restrict__ wts,
                  const float* __restrict__ b1,
                  float* __restrict__ h,
                  int O, int P, int K)
{
    const int bz = blockIdx.z;
    const float* Xb = X + (long)bz * strideX;
    const int o0 = blockIdx.y * 64;
    const int p0 = blockIdx.x * 128;

    GEMM_PROLOG_AND_LOOP(Wm, ldW, Xb, P, K)

    const int ot = o0 + ty * 4;

    const float4 bv4 = *(const float4*)&b1[ot];
    const float* gbase = Gt + (long)bz * MM * H1_;

    float hv[4][8];
    #pragma unroll
    for (int jj = 0; jj < 8; jj++) {
        const int n = p0 + ((jj < 4) ? (tx * 4 + jj) : (64 + tx * 4 + jj - 4));
        const int3   id = idx[(size_t)bz * NN + n];
        const float3 ww = wts[(size_t)bz * NN + n];
        float4 g0 = *(const float4*)&gbase[(long)id.x * H1_ + ot];
        float4 g1 = *(const float4*)&gbase[(long)id.y * H1_ + ot];
        float4 g2 = *(const float4*)&gbase[(long)id.z * H1_ + ot];
        hv[0][jj] = fmaxf(acc[0][jj] + ww.x * g0.x + ww.y * g1.x + ww.z * g2.x + bv4.x, 0.0f);
        hv[1][jj] = fmaxf(acc[1][jj] + ww.x * g0.y + ww.y * g1.y + ww.z * g2.y + bv4.y, 0.0f);
        hv[2][jj] = fmaxf(acc[2][jj] + ww.x * g0.z + ww.y * g1.z + ww.z * g2.z + bv4.z, 0.0f);
        hv[3][jj] = fmaxf(acc[3][jj] + ww.x * g0.w + ww.y * g1.w + ww.z * g2.w + bv4.w, 0.0f);
    }

    float* hb = h + (long)bz * H1_ * NN;
    const int ptA = p0 + tx * 4;
    const int ptB = p0 + 64 + tx * 4;
    #pragma unroll
    for (int i = 0; i < 4; i++) {
        *(float4*)&hb[(long)(ot + i) * NN + ptA] = *(float4*)&hv[i][0];
        *(float4*)&hb[(long)(ot + i) * NN + ptB] = *(float4*)&hv[i][4];
    }
}

// ---------------------------------------------------------------------------
// GEMM C: C stored (O, P) with bias + ReLU   [final output]
// ---------------------------------------------------------------------------
__global__ void __launch_bounds__(256)
gemm_op_kernel(const float* __restrict__ Wm, int ldW,
               const float* __restrict__ X, long strideX,
               float* __restrict__ C, long strideC,
               const float* __restrict__ bias,
               int O, int P, int K)
{
    const float* Xb = X + (long)blockIdx.z * strideX;
    float*       Cb = C + (long)blockIdx.z * strideC;
    const int o0 = blockIdx.y * 64;
    const int p0 = blockIdx.x * 128;

    GEMM_PROLOG_AND_LOOP(Wm, ldW, Xb, P, K)

    const int ot  = o0 + ty * 4;
    const int ptA = p0 + tx * 4;
    const int ptB = p0 + 64 + tx * 4;
    const float4 bv4 = *(const float4*)&bias[ot];
    const float bb[4] = {bv4.x, bv4.y, bv4.z, bv4.w};

    #pragma unroll
    for (int i = 0; i < 4; i++) {
        float4 vA, vB;
        vA.x = fmaxf(acc[i][0] + bb[i], 0.0f);
        vA.y = fmaxf(acc[i][1] + bb[i], 0.0f);
        vA.z = fmaxf(acc[i][2] + bb[i], 0.0f);
        vA.w = fmaxf(acc[i][3] + bb[i], 0.0f);
        vB.x = fmaxf(acc[i][4] + bb[i], 0.0f);
        vB.y = fmaxf(acc[i][5] + bb[i], 0.0f);
        vB.z = fmaxf(acc[i][6] + bb[i], 0.0f);
        vB.w = fmaxf(acc[i][7] + bb[i], 0.0f);
        *(float4*)&Cb[(long)(ot + i) * P + ptA] = vA;
        *(float4*)&Cb[(long)(ot + i) * P + ptB] = vB;
    }
}

// ---------------------------------------------------------------------------
// Launch
// ---------------------------------------------------------------------------
extern "C" void kernel_launch(void* const* d_in, const int* in_sizes, int n_in,
                              void* d_out, int out_size)
{
    const float* unknown      = (const float*)d_in[0];
    const float* known        = (const float*)d_in[1];
    const float* unknow_feats = (const float*)d_in[2];
    const float* known_feats  = (const float*)d_in[3];
    const float* W1           = (const float*)d_in[4];
    const float* b1           = (const float*)d_in[5];
    const float* W2           = (const float*)d_in[6];
    const float* b2           = (const float*)d_in[7];
    float* out = (float*)d_out;

    void *pGt, *pH, *pIdx, *pWts;
    cudaGetSymbolAddress(&pGt,  g_Gt);
    cudaGetSymbolAddress(&pH,   g_h);
    cudaGetSymbolAddress(&pIdx, g_idx);
    cudaGetSymbolAddress(&pWts, g_wts);

    const int knn_smem = 4 * MM * 4;   // 64KB
    cudaFuncSetAttribute(knn_kernel, cudaFuncAttributeMaxDynamicSharedMemorySize, knn_smem);

    // 1) 3-NN + weights (SoA + half-norm scoring, 1 thread/query)
    knn_kernel<<<dim3(NN / 256, BB), 256, knn_smem>>>(
        unknown, known, (int3*)pIdx, (float3*)pWts);

    // 2) Gt[b,m,o] = sum_c W1[o,c] * known_feats[b,c,m]  (c in [0,256)), (P,O) store
    gemm_po_kernel<<<dim3(MM / 128, H1_ / 64, BB), 256>>>(
        W1, C1_ + C2_, known_feats, (long)C2_ * MM,
        (float*)pGt, (long)MM * H1_, H1_, MM, C2_);

    // 3+4) h = relu( W1b @ unknow_feats + gather-interp(Gt) + b1 ), (O,P) store
    gemm_fused_kernel<<<dim3(NN / 128, H1_ / 64, BB), 256>>>(
        W1 + C2_, C1_ + C2_, unknow_feats, (long)C1_ * NN,
        (const float*)pGt, (const int3*)pIdx, (const float3*)pWts,
        b1, (float*)pH, H1_, NN, C1_);

    // 5) out = relu(W2 @ h + b2), (O,P) store
    gemm_op_kernel<<<dim3(NN / 128, H2_ / 64, BB), 256>>>(
        W2, H1_, (const float*)pH, (long)H1_ * NN,
        out, (long)H2_ * NN, b2, H2_, NN, H1_);
}

// round 17
// speedup vs baseline: 1.8479x; 1.0464x over previous
#include <cuda_runtime.h>
#include <cuda_bf16.h>
#include <cstdint>

#define BB  2
#define NN  16384
#define MM  4096
#define C1_ 128
#define C2_ 256
#define H1_ 256
#define H2_ 128

// ---------------------------------------------------------------------------
// Scratch
// ---------------------------------------------------------------------------
__device__ int3   g_idx[BB * NN];
__device__ float3 g_wts[BB * NN];
__device__ float  g_Gt[(size_t)BB * MM * H1_];   // (B, M, H1) point-major
__device__ float  g_h [(size_t)BB * H1_ * NN];   // (B, H1, N) channel-major

// ---------------------------------------------------------------------------
// cp.async helpers
// ---------------------------------------------------------------------------
__device__ __forceinline__ uint32_t s2u(const void* p) {
    return (uint32_t)__cvta_generic_to_shared(p);
}
__device__ __forceinline__ void cpa16(uint32_t dst, const float* src) {
    asm volatile("cp.async.cg.shared.global [%0], [%1], 16;" :: "r"(dst), "l"(src));
}
__device__ __forceinline__ void cpa_commit() {
    asm volatile("cp.async.commit_group;" ::: "memory");
}
__device__ __forceinline__ void cpa_wait0() {
    asm volatile("cp.async.wait_group 0;" ::: "memory");
}

// ---------------------------------------------------------------------------
// ins3: keep 3 smallest (score, index), stable earliest-wins on ties
// ---------------------------------------------------------------------------
__device__ __forceinline__ void ins3(float d, int i,
                                     float& s0, float& s1, float& s2,
                                     int& i0, int& i1, int& i2) {
    if (d < s2) {
        if (d < s1) {
            s2 = s1; i2 = i1;
            if (d < s0) { s1 = s0; i1 = i0; s0 = d; i0 = i; }
            else        { s1 = d;  i1 = i; }
        } else { s2 = d; i2 = i; }
    }
}

// ---------------------------------------------------------------------------
// kNN (SoA + half-norm score, verified): 1 thread per query.
// ---------------------------------------------------------------------------
__global__ void __launch_bounds__(256)
knn_kernel(const float* __restrict__ unknown,
           const float* __restrict__ known,
           int3* __restrict__ idx_out,
           float3* __restrict__ wts_out)
{
    extern __shared__ float dsm[];
    float* sx = dsm;
    float* sy = dsm + MM;
    float* sz = dsm + 2 * MM;
    float* sh = dsm + 3 * MM;

    const int b   = blockIdx.y;
    const int tid = threadIdx.x;

    const float* kb = known + (size_t)b * MM * 3;
    for (int i = tid; i < MM; i += 256) {
        float x = kb[i * 3 + 0], y = kb[i * 3 + 1], z = kb[i * 3 + 2];
        sx[i] = x; sy[i] = y; sz[i] = z;
        sh[i] = 0.5f * (x * x + y * y + z * z);
    }
    __syncthreads();

    const int n = blockIdx.x * 256 + tid;
    const float3 p = ((const float3*)unknown)[(size_t)b * NN + n];
    const float nax = -p.x, nay = -p.y, naz = -p.z;

    float s0 = 1e30f, s1 = 1e30f, s2 = 1e30f;
    int i0 = 0, i1 = 0, i2 = 0;

    const float4* x4 = (const float4*)sx;
    const float4* y4 = (const float4*)sy;
    const float4* z4 = (const float4*)sz;
    const float4* h4 = (const float4*)sh;

    #pragma unroll 2
    for (int j = 0; j < MM / 4; j++) {
        float4 Xv = x4[j], Yv = y4[j], Zv = z4[j], Hv = h4[j];
        float t0 = fmaf(Xv.x, nax, fmaf(Yv.x, nay, fmaf(Zv.x, naz, Hv.x)));
        float t1 = fmaf(Xv.y, nax, fmaf(Yv.y, nay, fmaf(Zv.y, naz, Hv.y)));
        float t2 = fmaf(Xv.z, nax, fmaf(Yv.z, nay, fmaf(Zv.z, naz, Hv.z)));
        float t3 = fmaf(Xv.w, nax, fmaf(Yv.w, nay, fmaf(Zv.w, naz, Hv.w)));
        float m = fminf(fminf(t0, t1), fminf(t2, t3));
        if (m < s2) {
            int mb = j * 4;
            ins3(t0, mb + 0, s0, s1, s2, i0, i1, i2);
            ins3(t1, mb + 1, s0, s1, s2, i0, i1, i2);
            ins3(t2, mb + 2, s0, s1, s2, i0, i1, i2);
            ins3(t3, mb + 3, s0, s1, s2, i0, i1, i2);
        }
    }

    float dx, dy, dz;
    dx = sx[i0] - p.x; dy = sy[i0] - p.y; dz = sz[i0] - p.z;
    float d0 = dx * dx + dy * dy + dz * dz;
    dx = sx[i1] - p.x; dy = sy[i1] - p.y; dz = sz[i1] - p.z;
    float d1 = dx * dx + dy * dy + dz * dz;
    dx = sx[i2] - p.x; dy = sy[i2] - p.y; dz = sz[i2] - p.z;
    float d2 = dx * dx + dy * dy + dz * dz;

    float r0 = 1.0f / (sqrtf(d0) + 1e-8f);
    float r1 = 1.0f / (sqrtf(d1) + 1e-8f);
    float r2 = 1.0f / (sqrtf(d2) + 1e-8f);
    float rs = 1.0f / (r0 + r1 + r2);

    idx_out[(size_t)b * NN + n] = make_int3(i0, i1, i2);
    wts_out[(size_t)b * NN + n] = make_float3(r0 * rs, r1 * rs, r2 * rs);
}

// ---------------------------------------------------------------------------
// 4x8 GEMM core (R11/R15 verified): tile 64(O) x 128(P) x 16. Used by gemm_po.
// ---------------------------------------------------------------------------
#define GEMM_PROLOG_AND_LOOP(Wm, ldW, Xb, P, K)                                     \
    __shared__ float Ws[2][16][64];                                                 \
    __shared__ float Xs[2][16][128];                                                \
    const int t  = threadIdx.x;                                                     \
    const int tx = t & 15;                                                          \
    const int ty = t >> 4;                                                          \
    const int wo = t >> 2, wk = (t & 3) * 4;                                        \
    const int xk = t >> 4, xp = (t & 15) * 8;                                       \
    const float* wsrc = (Wm) + (long)(o0 + wo) * (ldW) + wk;                        \
    const float* xsrc = (Xb) + (long)xk * (P) + p0 + xp;                            \
    float acc[4][8] = {};                                                           \
    {                                                                               \
        float4 wv = *(const float4*)&wsrc[0];                                       \
        Ws[0][wk + 0][wo] = wv.x; Ws[0][wk + 1][wo] = wv.y;                         \
        Ws[0][wk + 2][wo] = wv.z; Ws[0][wk + 3][wo] = wv.w;                         \
        *(float4*)&Xs[0][xk][xp]     = *(const float4*)&xsrc[0];                    \
        *(float4*)&Xs[0][xk][xp + 4] = *(const float4*)&xsrc[4];                    \
    }                                                                               \
    __syncthreads();                                                                \
    int buf = 0;                                                                    \
    for (int k0 = 0; k0 < (K); k0 += 16) {                                          \
        const bool has_next = (k0 + 16 < (K));                                      \
        float4 wv, x0, x1;                                                          \
        if (has_next) {                                                             \
            wv = *(const float4*)&wsrc[k0 + 16];                                    \
            x0 = *(const float4*)&xsrc[(long)(k0 + 16) * (P)];                      \
            x1 = *(const float4*)&xsrc[(long)(k0 + 16) * (P) + 4];                  \
        }                                                                           \
        _Pragma("unroll")                                                           \
        for (int k = 0; k < 16; k++) {                                              \
            float a[4], bv[8];                                                      \
            *(float4*)&a[0]  = *(const float4*)&Ws[buf][k][ty * 4];                 \
            *(float4*)&bv[0] = *(const float4*)&Xs[buf][k][tx * 4];                 \
            *(float4*)&bv[4] = *(const float4*)&Xs[buf][k][64 + tx * 4];            \
            _Pragma("unroll")                                                       \
            for (int i = 0; i < 4; i++)                                             \
                _Pragma("unroll")                                                   \
                for (int j = 0; j < 8; j++)                                         \
                    acc[i][j] = fmaf(a[i], bv[j], acc[i][j]);                       \
        }                                                                           \
        if (has_next) {                                                             \
            int nb = buf ^ 1;                                                       \
            Ws[nb][wk + 0][wo] = wv.x; Ws[nb][wk + 1][wo] = wv.y;                   \
            Ws[nb][wk + 2][wo] = wv.z; Ws[nb][wk + 3][wo] = wv.w;                   \
            *(float4*)&Xs[nb][xk][xp]     = x0;                                     \
            *(float4*)&Xs[nb][xk][xp + 4] = x1;                                     \
            __syncthreads();                                                        \
            buf = nb;                                                               \
        }                                                                           \
    }

// ---------------------------------------------------------------------------
// 8x8 GEMM core: tile 128(O) x 128(P) x 16, 256 threads, cp.async X staging
// (no prefetch regs for X), W via LDG+STS transpose (8 regs). 2 CTAs/SM.
// ---------------------------------------------------------------------------
#define GEMM8_PROLOG_AND_LOOP(Wm, ldW, Xb, P, K)                                    \
    __shared__ float Ws[2][16][128];                                                \
    __shared__ float Xs[2][16][128];                                                \
    const int t  = threadIdx.x;                                                     \
    const int tx = t & 15;                                                          \
    const int ty = t >> 4;                                                          \
    const int wo = t >> 2, wk = (t & 3) * 4;                                        \
    const int xk = t >> 4, xp = (t & 15) * 8;                                       \
    const float* wsrc0 = (Wm) + (long)(o0 + wo) * (ldW) + wk;                       \
    const float* wsrc1 = (Wm) + (long)(o0 + 64 + wo) * (ldW) + wk;                  \
    const float* xsrc  = (Xb) + (long)xk * (P) + p0 + xp;                           \
    float acc[8][8] = {};                                                           \
    {                                                                               \
        uint32_t d0 = s2u(&Xs[0][xk][xp]);                                          \
        cpa16(d0, xsrc); cpa16(d0 + 16, xsrc + 4);                                  \
        cpa_commit();                                                               \
        float4 wa = *(const float4*)&wsrc0[0];                                      \
        float4 wb = *(const float4*)&wsrc1[0];                                      \
        Ws[0][wk + 0][wo] = wa.x; Ws[0][wk + 1][wo] = wa.y;                         \
        Ws[0][wk + 2][wo] = wa.z; Ws[0][wk + 3][wo] = wa.w;                         \
        Ws[0][wk + 0][64 + wo] = wb.x; Ws[0][wk + 1][64 + wo] = wb.y;               \
        Ws[0][wk + 2][64 + wo] = wb.z; Ws[0][wk + 3][64 + wo] = wb.w;               \
        cpa_wait0();                                                                \
        __syncthreads();                                                            \
    }                                                                               \
    int buf = 0;                                                                    \
    for (int k0 = 0; k0 < (K); k0 += 16) {                                          \
        const bool has_next = (k0 + 16 < (K));                                      \
        float4 wa, wb;                                                              \
        if (has_next) {                                                             \
            uint32_t dn = s2u(&Xs[buf ^ 1][xk][xp]);                                \
            const float* xs = xsrc + (long)(k0 + 16) * (P);                         \
            cpa16(dn, xs); cpa16(dn + 16, xs + 4);                                  \
            cpa_commit();                                                           \
            wa = *(const float4*)&wsrc0[k0 + 16];                                   \
            wb = *(const float4*)&wsrc1[k0 + 16];                                   \
        }                                                                           \
        _Pragma("unroll")                                                           \
        for (int k = 0; k < 16; k++) {                                              \
            float a[8], bv[8];                                                      \
            *(float4*)&a[0]  = *(const float4*)&Ws[buf][k][ty * 4];                 \
            *(float4*)&a[4]  = *(const float4*)&Ws[buf][k][64 + ty * 4];            \
            *(float4*)&bv[0] = *(const float4*)&Xs[buf][k][tx * 4];                 \
            *(float4*)&bv[4] = *(const float4*)&Xs[buf][k][64 + tx * 4];            \
            _Pragma("unroll")                                                       \
            for (int i = 0; i < 8; i++)                                             \
                _Pragma("unroll")                                                   \
                for (int j = 0; j < 8; j++)                                         \
                    acc[i][j] = fmaf(a[i], bv[j], acc[i][j]);                       \
        }                                                                           \
        if (has_next) {                                                             \
            int nb = buf ^ 1;                                                       \
            Ws[nb][wk + 0][wo] = wa.x; Ws[nb][wk + 1][wo] = wa.y;                   \
            Ws[nb][wk + 2][wo] = wa.z; Ws[nb][wk + 3][wo] = wa.w;                   \
            Ws[nb][wk + 0][64 + wo] = wb.x; Ws[nb][wk + 1][64 + wo] = wb.y;         \
            Ws[nb][wk + 2][64 + wo] = wb.z; Ws[nb][wk + 3][64 + wo] = wb.w;         \
            cpa_wait0();                                                            \
            __syncthreads();                                                        \
            buf = nb;                                                               \
        }                                                                           \
    }

// ---------------------------------------------------------------------------
// GEMM A (4x8 core): C stored point-major (P, O)   [for Gt]
// ---------------------------------------------------------------------------
__global__ void __launch_bounds__(256)
gemm_po_kernel(const float* __restrict__ Wm, int ldW,
               const float* __restrict__ X, long strideX,
               float* __restrict__ C, long strideC,
               int O, int P, int K)
{
    const float* Xb = X + (long)blockIdx.z * strideX;
    float*       Cb = C + (long)blockIdx.z * strideC;
    const int o0 = blockIdx.y * 64;
    const int p0 = blockIdx.x * 128;

    GEMM_PROLOG_AND_LOOP(Wm, ldW, Xb, P, K)

    const int ot  = o0 + ty * 4;
    const int ptA = p0 + tx * 4;
    const int ptB = p0 + 64 + tx * 4;
    #pragma unroll
    for (int j = 0; j < 4; j++) {
        float4 vA = make_float4(acc[0][j],     acc[1][j],     acc[2][j],     acc[3][j]);
        float4 vB = make_float4(acc[0][j + 4], acc[1][j + 4], acc[2][j + 4], acc[3][j + 4]);
        *(float4*)&Cb[(long)(ptA + j) * O + ot] = vA;
        *(float4*)&Cb[(long)(ptB + j) * O + ot] = vB;
    }
}

// ---------------------------------------------------------------------------
// GEMM B (8x8 core, fused): Ut tile in regs + gather-interp Gt + bias + ReLU,
// stored channel-major (O, P) into h. Epilogue in two O-halves.
// ---------------------------------------------------------------------------
__global__ void __launch_bounds__(256, 2)
gemm_fused8_kernel(const float* __restrict__ Wm, int ldW,
                   const float* __restrict__ X, long strideX,
                   const float* __restrict__ Gt,
                   const int3* __restrict__ idx,
                   const float3* __restrict__ wts,
                   const float* __restrict__ b1,
                   float* __restrict__ h,
                   int O, int P, int K)
{
    const int bz = blockIdx.z;
    const float* Xb = X + (long)bz * strideX;
    const int o0 = blockIdx.y * 128;
    const int p0 = blockIdx.x * 128;

    GEMM8_PROLOG_AND_LOOP(Wm, ldW, Xb, P, K)

    const float* gbase = Gt + (long)bz * MM * H1_;
    float* hb = h + (long)bz * H1_ * NN;

    #pragma unroll
    for (int ih = 0; ih < 2; ih++) {
        const int ot = o0 + ih * 64 + ty * 4;
        const float4 bv4 = *(const float4*)&b1[ot];

        float hv[4][8];
        #pragma unroll
        for (int jj = 0; jj < 8; jj++) {
            const int n = p0 + ((jj < 4) ? (tx * 4 + jj) : (64 + tx * 4 + jj - 4));
            const int3   id = idx[(size_t)bz * NN + n];
            const float3 ww = wts[(size_t)bz * NN + n];
            float4 g0 = *(const float4*)&gbase[(long)id.x * H1_ + ot];
            float4 g1 = *(const float4*)&gbase[(long)id.y * H1_ + ot];
            float4 g2 = *(const float4*)&gbase[(long)id.z * H1_ + ot];
            hv[0][jj] = fmaxf(acc[ih * 4 + 0][jj] + ww.x * g0.x + ww.y * g1.x + ww.z * g2.x + bv4.x, 0.0f);
            hv[1][jj] = fmaxf(acc[ih * 4 + 1][jj] + ww.x * g0.y + ww.y * g1.y + ww.z * g2.y + bv4.y, 0.0f);
            hv[2][jj] = fmaxf(acc[ih * 4 + 2][jj] + ww.x * g0.z + ww.y * g1.z + ww.z * g2.z + bv4.z, 0.0f);
            hv[3][jj] = fmaxf(acc[ih * 4 + 3][jj] + ww.x * g0.w + ww.y * g1.w + ww.z * g2.w + bv4.w, 0.0f);
        }

        const int ptA = p0 + tx * 4;
        const int ptB = p0 + 64 + tx * 4;
        #pragma unroll
        for (int i = 0; i < 4; i++) {
            *(float4*)&hb[(long)(ot + i) * NN + ptA] = *(float4*)&hv[i][0];
            *(float4*)&hb[(long)(ot + i) * NN + ptB] = *(float4*)&hv[i][4];
        }
    }
}

// ---------------------------------------------------------------------------
// GEMM C (8x8 core): C stored (O, P) with bias + ReLU   [final output]
// ---------------------------------------------------------------------------
__global__ void __launch_bounds__(256, 2)
gemm_op8_kernel(const float* __restrict__ Wm, int ldW,
                const float* __restrict__ X, long strideX,
                float* __restrict__ C, long strideC,
                const float* __restrict__ bias,
                int O, int P, int K)
{
    const float* Xb = X + (long)blockIdx.z * strideX;
    float*       Cb = C + (long)blockIdx.z * strideC;
    const int o0 = blockIdx.y * 128;
    const int p0 = blockIdx.x * 128;

    GEMM8_PROLOG_AND_LOOP(Wm, ldW, Xb, P, K)

    const int ptA = p0 + tx * 4;
    const int ptB = p0 + 64 + tx * 4;

    #pragma unroll
    for (int ih = 0; ih < 2; ih++) {
        const int ot = o0 + ih * 64 + ty * 4;
        const float4 bv4 = *(const float4*)&bias[ot];
        const float bb[4] = {bv4.x, bv4.y, bv4.z, bv4.w};

        #pragma unroll
        for (int i = 0; i < 4; i++) {
            float4 vA, vB;
            vA.x = fmaxf(acc[ih * 4 + i][0] + bb[i], 0.0f);
            vA.y = fmaxf(acc[ih * 4 + i][1] + bb[i], 0.0f);
            vA.z = fmaxf(acc[ih * 4 + i][2] + bb[i], 0.0f);
            vA.w = fmaxf(acc[ih * 4 + i][3] + bb[i], 0.0f);
            vB.x = fmaxf(acc[ih * 4 + i][4] + bb[i], 0.0f);
            vB.y = fmaxf(acc[ih * 4 + i][5] + bb[i], 0.0f);
            vB.z = fmaxf(acc[ih * 4 + i][6] + bb[i], 0.0f);
            vB.w = fmaxf(acc[ih * 4 + i][7] + bb[i], 0.0f);
            *(float4*)&Cb[(long)(ot + i) * P + ptA] = vA;
            *(float4*)&Cb[(long)(ot + i) * P + ptB] = vB;
        }
    }
}

// ---------------------------------------------------------------------------
// Launch
// ---------------------------------------------------------------------------
extern "C" void kernel_launch(void* const* d_in, const int* in_sizes, int n_in,
                              void* d_out, int out_size)
{
    const float* unknown      = (const float*)d_in[0];
    const float* known        = (const float*)d_in[1];
    const float* unknow_feats = (const float*)d_in[2];
    const float* known_feats  = (const float*)d_in[3];
    const float* W1           = (const float*)d_in[4];
    const float* b1           = (const float*)d_in[5];
    const float* W2           = (const float*)d_in[6];
    const float* b2           = (const float*)d_in[7];
    float* out = (float*)d_out;

    void *pGt, *pH, *pIdx, *pWts;
    cudaGetSymbolAddress(&pGt,  g_Gt);
    cudaGetSymbolAddress(&pH,   g_h);
    cudaGetSymbolAddress(&pIdx, g_idx);
    cudaGetSymbolAddress(&pWts, g_wts);

    const int knn_smem = 4 * MM * 4;   // 64KB
    cudaFuncSetAttribute(knn_kernel, cudaFuncAttributeMaxDynamicSharedMemorySize, knn_smem);

    // 1) 3-NN + weights (SoA + half-norm scoring, 1 thread/query)
    knn_kernel<<<dim3(NN / 256, BB), 256, knn_smem>>>(
        unknown, known, (int3*)pIdx, (float3*)pWts);

    // 2) Gt[b,m,o] = sum_c W1[o,c] * known_feats[b,c,m]  (4x8 core, (P,O) store)
    gemm_po_kernel<<<dim3(MM / 128, H1_ / 64, BB), 256>>>(
        W1, C1_ + C2_, known_feats, (long)C2_ * MM,
        (float*)pGt, (long)MM * H1_, H1_, MM, C2_);

    // 3+4) h = relu( W1b @ unknow_feats + gather-interp(Gt) + b1 )  (8x8 core)
    gemm_fused8_kernel<<<dim3(NN / 128, H1_ / 128, BB), 256>>>(
        W1 + C2_, C1_ + C2_, unknow_feats, (long)C1_ * NN,
        (const float*)pGt, (const int3*)pIdx, (const float3*)pWts,
        b1, (float*)pH, H1_, NN, C1_);

    // 5) out = relu(W2 @ h + b2)  (8x8 core, (O,P) store)
    gemm_op8_kernel<<<dim3(NN / 128, H2_ / 128, BB), 256>>>(
        W2, H1_, (const float*)pH, (long)H1_ * NN,
        out, (long)H2_ * NN, b2, H2_, NN, H1_);
}